// round 2
// baseline (speedup 1.0000x reference)
#include <cuda_runtime.h>
#include <cuda_bf16.h>

#define N_NODES 50000
#define F_IN    256
#define F_OUT   64
#define N_EDGES 800000

// Scratch for XW = X @ W  (50000 x 64 fp32 = 12.8 MB). Static device global:
// allocation-free per harness rules.
__device__ float g_xw[(size_t)N_NODES * F_OUT];

// ---------------------------------------------------------------------------
// GEMM: XW[N, 64] = X[N, 256] @ W[256, 64]   (fp32, CUDA cores)
// Block: 256 threads computes a 128x64 output tile. Micro-tile 8 rows x 4 cols.
// K processed in chunks of 32, inner loop unrolled by 4 with float4 smem reads.
// ---------------------------------------------------------------------------
#define TM 128
#define TK 32
#define XS_STRIDE (TK + 4)   // 36 floats: keeps float4 row alignment (36*4 % 16 == 0)

__global__ __launch_bounds__(256) void gemm_kernel(const float* __restrict__ X,
                                                   const float* __restrict__ W) {
    __shared__ float Xs[TM][XS_STRIDE];   // 128*36*4 = 18432 B
    __shared__ float Ws[TK][F_OUT];       // 32*64*4  =  8192 B

    const int tid = threadIdx.x;
    const int tx = tid & 15;   // col group: cols [tx*4, tx*4+4)
    const int ty = tid >> 4;   // row group: rows [ty*8, ty*8+8)
    const int rowBase = blockIdx.x * TM;

    float acc[8][4];
#pragma unroll
    for (int i = 0; i < 8; i++)
#pragma unroll
        for (int j = 0; j < 4; j++) acc[i][j] = 0.0f;

    for (int k0 = 0; k0 < F_IN; k0 += TK) {
        // Load W chunk: 32x64 floats = 512 float4, 2 per thread. Coalesced.
#pragma unroll
        for (int i = 0; i < 2; i++) {
            int idx = tid + i * 256;       // float4 index 0..511
            int r = idx >> 4;              // 16 float4 per W row
            int c = idx & 15;
            *(float4*)&Ws[r][c * 4] =
                *(const float4*)(W + (size_t)(k0 + r) * F_OUT + c * 4);
        }
        // Load X tile: 128x32 floats = 1024 float4, 4 per thread. Coalesced.
#pragma unroll
        for (int i = 0; i < 4; i++) {
            int idx = tid + i * 256;       // float4 index 0..1023
            int r = idx >> 3;              // 8 float4 per tile row
            int c = idx & 7;
            int gr = rowBase + r;
            float4 v = make_float4(0.f, 0.f, 0.f, 0.f);
            if (gr < N_NODES)
                v = *(const float4*)(X + (size_t)gr * F_IN + k0 + c * 4);
            *(float4*)&Xs[r][c * 4] = v;
        }
        __syncthreads();

#pragma unroll
        for (int k = 0; k < TK; k += 4) {
            const float4 b0 = *(const float4*)&Ws[k + 0][tx * 4];
            const float4 b1 = *(const float4*)&Ws[k + 1][tx * 4];
            const float4 b2 = *(const float4*)&Ws[k + 2][tx * 4];
            const float4 b3 = *(const float4*)&Ws[k + 3][tx * 4];
#pragma unroll
            for (int i = 0; i < 8; i++) {
                const float4 a = *(const float4*)&Xs[ty * 8 + i][k];
                acc[i][0] += a.x * b0.x; acc[i][0] += a.y * b1.x;
                acc[i][0] += a.z * b2.x; acc[i][0] += a.w * b3.x;
                acc[i][1] += a.x * b0.y; acc[i][1] += a.y * b1.y;
                acc[i][1] += a.z * b2.y; acc[i][1] += a.w * b3.y;
                acc[i][2] += a.x * b0.z; acc[i][2] += a.y * b1.z;
                acc[i][2] += a.z * b2.z; acc[i][2] += a.w * b3.z;
                acc[i][3] += a.x * b0.w; acc[i][3] += a.y * b1.w;
                acc[i][3] += a.z * b2.w; acc[i][3] += a.w * b3.w;
            }
        }
        __syncthreads();
    }

    // Store 8x4 micro-tile as float4 rows (coalesced within the 64-wide row).
#pragma unroll
    for (int i = 0; i < 8; i++) {
        int gr = rowBase + ty * 8 + i;
        if (gr < N_NODES) {
            float4 v = make_float4(acc[i][0], acc[i][1], acc[i][2], acc[i][3]);
            *(float4*)(g_xw + (size_t)gr * F_OUT + tx * 4) = v;
        }
    }
}

// ---------------------------------------------------------------------------
// Scatter: out[edge_row[e]] += edge_vals[e] * XW[edge_col[e]]
// 16 threads per edge, one float4 (16 B) each -> covers the 64-wide row.
// Vectorized float4 atomicAdd (sm_90+) to cut atomic op count 4x.
// XW (12.8 MB) and out (12.8 MB) are both L2-resident -> L2-bound phase.
// ---------------------------------------------------------------------------
__global__ __launch_bounds__(256) void scatter_kernel(const int* __restrict__ erow,
                                                      const int* __restrict__ ecol,
                                                      const float* __restrict__ evals,
                                                      float* __restrict__ out) {
    const int gid = blockIdx.x * blockDim.x + threadIdx.x;
    const int e = gid >> 4;
    const int lane = gid & 15;
    if (e >= N_EDGES) return;

    const int r = __ldg(erow + e);
    const int c = __ldg(ecol + e);
    const float v = __ldg(evals + e);

    const float4 x = *(const float4*)(g_xw + (size_t)c * F_OUT + lane * 4);
    float4 m = make_float4(x.x * v, x.y * v, x.z * v, x.w * v);

    atomicAdd((float4*)(out + (size_t)r * F_OUT + lane * 4), m);
}

// ---------------------------------------------------------------------------
// Launch
// ---------------------------------------------------------------------------
extern "C" void kernel_launch(void* const* d_in, const int* in_sizes, int n_in,
                              void* d_out, int out_size) {
    const float* X     = (const float*)d_in[0];
    const float* W     = (const float*)d_in[1];
    const int*   erow  = (const int*)d_in[2];
    const int*   ecol  = (const int*)d_in[3];
    const float* evals = (const float*)d_in[4];
    float* out = (float*)d_out;

    // d_out is poisoned; atomics need zeros. Memset node is graph-capturable.
    cudaMemsetAsync(d_out, 0, (size_t)out_size * sizeof(float));

    gemm_kernel<<<(N_NODES + TM - 1) / TM, 256>>>(X, W);

    const int total = N_EDGES * 16;  // 16 threads per edge
    scatter_kernel<<<(total + 255) / 256, 256>>>(erow, ecol, evals, out);
}

// round 3
// speedup vs baseline: 1.0444x; 1.0444x over previous
#include <cuda_runtime.h>
#include <cuda_bf16.h>
#include <cstdint>

#define N_NODES 50000
#define F_IN    256
#define F_OUT   64
#define N_EDGES 800000

// Scratch for XW = X @ W  (50000 x 64 fp32 = 12.8 MB).
__device__ float g_xw[(size_t)N_NODES * F_OUT];

// ---------------------------------------------------------------------------
// TF32 tensor-core GEMM: XW[N,64] = X[N,256] @ W[256,64]
// Block: 256 thr (8 warps). Tile: 128 rows x 64 cols, K-chunk 32.
// Warp w computes rows [16w, 16w+16) x all 64 cols via mma.m16n8k8 (8 n-tiles).
// ---------------------------------------------------------------------------
#define GTM 128
#define GTK 32
#define XS_STR 36   // 144B row: float4-aligned, conflict-free A-frag loads
#define WS_STR 72   // 288B row: float4-aligned, conflict-free B-frag loads

__device__ __forceinline__ uint32_t f2tf32(float f) {
    uint32_t u;
    asm("cvt.rna.tf32.f32 %0, %1;" : "=r"(u) : "f"(f));
    return u;
}

__global__ __launch_bounds__(256) void gemm_tf32_kernel(const float* __restrict__ X,
                                                        const float* __restrict__ W) {
    __shared__ float Xs[GTM][XS_STR];   // 18432 B
    __shared__ float Ws[GTK][WS_STR];   //  9216 B

    const int tid  = threadIdx.x;
    const int warp = tid >> 5;
    const int lane = tid & 31;
    const int rowBase = blockIdx.x * GTM;
    const int qid  = lane >> 2;   // 0..7
    const int qsub = lane & 3;    // 0..3

    // 8 n-tiles x 4 fp32 accumulators
    float acc[8][4];
#pragma unroll
    for (int j = 0; j < 8; j++)
#pragma unroll
        for (int i = 0; i < 4; i++) acc[j][i] = 0.0f;

    for (int k0 = 0; k0 < F_IN; k0 += GTK) {
        // Load W chunk 32x64 floats = 512 float4, 2 per thread, coalesced.
#pragma unroll
        for (int i = 0; i < 2; i++) {
            int idx = tid + i * 256;
            int r = idx >> 4, c = idx & 15;
            *(float4*)&Ws[r][c * 4] =
                *(const float4*)(W + (size_t)(k0 + r) * F_OUT + c * 4);
        }
        // Load X tile 128x32 floats = 1024 float4, 4 per thread, coalesced.
#pragma unroll
        for (int i = 0; i < 4; i++) {
            int idx = tid + i * 256;
            int r = idx >> 3, c = idx & 7;
            int gr = rowBase + r;
            float4 v = make_float4(0.f, 0.f, 0.f, 0.f);
            if (gr < N_NODES)
                v = *(const float4*)(X + (size_t)gr * F_IN + k0 + c * 4);
            *(float4*)&Xs[r][c * 4] = v;
        }
        __syncthreads();

#pragma unroll
        for (int kk = 0; kk < GTK; kk += 8) {
            // A fragment (m16k8, row-major): rows warp*16 + qid (+8), cols kk+qsub (+4)
            const int ar = warp * 16 + qid;
            const uint32_t a0 = f2tf32(Xs[ar    ][kk + qsub    ]);
            const uint32_t a1 = f2tf32(Xs[ar + 8][kk + qsub    ]);
            const uint32_t a2 = f2tf32(Xs[ar    ][kk + qsub + 4]);
            const uint32_t a3 = f2tf32(Xs[ar + 8][kk + qsub + 4]);
#pragma unroll
            for (int j = 0; j < 8; j++) {
                // B fragment (k8n8, col-major): k = kk+qsub (+4), n = j*8 + qid
                const uint32_t b0 = f2tf32(Ws[kk + qsub    ][j * 8 + qid]);
                const uint32_t b1 = f2tf32(Ws[kk + qsub + 4][j * 8 + qid]);
                asm volatile(
                    "mma.sync.aligned.m16n8k8.row.col.f32.tf32.tf32.f32 "
                    "{%0,%1,%2,%3}, {%4,%5,%6,%7}, {%8,%9}, {%0,%1,%2,%3};"
                    : "+f"(acc[j][0]), "+f"(acc[j][1]), "+f"(acc[j][2]), "+f"(acc[j][3])
                    : "r"(a0), "r"(a1), "r"(a2), "r"(a3), "r"(b0), "r"(b1));
            }
        }
        __syncthreads();
    }

    // Store C fragments: c0,c1 -> (row, 2*qsub..+1), c2,c3 -> (row+8, same cols)
    const int crow = rowBase + warp * 16 + qid;
#pragma unroll
    for (int j = 0; j < 8; j++) {
        const int ccol = j * 8 + 2 * qsub;
        if (crow < N_NODES)
            *(float2*)(g_xw + (size_t)crow * F_OUT + ccol) =
                make_float2(acc[j][0], acc[j][1]);
        if (crow + 8 < N_NODES)
            *(float2*)(g_xw + (size_t)(crow + 8) * F_OUT + ccol) =
                make_float2(acc[j][2], acc[j][3]);
    }
}

// ---------------------------------------------------------------------------
// Scatter: out[erow[e]] += evals[e] * XW[ecol[e]]
// 4 threads/edge; each thread: 4 independent float4 gathers + 4 float4 atomics
// (MLP=4 for latency hiding; 4x fewer threads + index loads than 16/edge).
// ---------------------------------------------------------------------------
__global__ __launch_bounds__(256) void scatter_kernel(const int* __restrict__ erow,
                                                      const int* __restrict__ ecol,
                                                      const float* __restrict__ evals,
                                                      float* __restrict__ out) {
    const int gid  = blockIdx.x * blockDim.x + threadIdx.x;
    const int e    = gid >> 2;
    const int lane = gid & 3;     // covers float4 slots [lane*4, lane*4+4)
    if (e >= N_EDGES) return;

    const int   r = __ldg(erow + e);
    const int   c = __ldg(ecol + e);
    const float v = __ldg(evals + e);

    const float4* src = (const float4*)(g_xw + (size_t)c * F_OUT) + lane * 4;
    float4*       dst = (float4*)(out + (size_t)r * F_OUT) + lane * 4;

    // 4 independent gathers issued back-to-back (MLP=4)
    const float4 x0 = __ldg(src + 0);
    const float4 x1 = __ldg(src + 1);
    const float4 x2 = __ldg(src + 2);
    const float4 x3 = __ldg(src + 3);

    atomicAdd(dst + 0, make_float4(x0.x * v, x0.y * v, x0.z * v, x0.w * v));
    atomicAdd(dst + 1, make_float4(x1.x * v, x1.y * v, x1.z * v, x1.w * v));
    atomicAdd(dst + 2, make_float4(x2.x * v, x2.y * v, x2.z * v, x2.w * v));
    atomicAdd(dst + 3, make_float4(x3.x * v, x3.y * v, x3.z * v, x3.w * v));
}

// ---------------------------------------------------------------------------
// Launch
// ---------------------------------------------------------------------------
extern "C" void kernel_launch(void* const* d_in, const int* in_sizes, int n_in,
                              void* d_out, int out_size) {
    const float* X     = (const float*)d_in[0];
    const float* W     = (const float*)d_in[1];
    const int*   erow  = (const int*)d_in[2];
    const int*   ecol  = (const int*)d_in[3];
    const float* evals = (const float*)d_in[4];
    float* out = (float*)d_out;

    cudaMemsetAsync(d_out, 0, (size_t)out_size * sizeof(float));

    gemm_tf32_kernel<<<(N_NODES + GTM - 1) / GTM, 256>>>(X, W);

    const int total = N_EDGES * 4;  // 4 threads per edge
    scatter_kernel<<<(total + 255) / 256, 256>>>(erow, ecol, evals, out);
}

// round 4
// speedup vs baseline: 1.1901x; 1.1395x over previous
#include <cuda_runtime.h>
#include <cuda_bf16.h>
#include <cstdint>

#define N_NODES 50000
#define F_IN    256
#define F_OUT   64
#define N_EDGES 800000

#define SCAN_CHUNK 4096                 // 256 threads * 16 items
#define SCAN_NB    ((N_NODES + SCAN_CHUNK - 1) / SCAN_CHUNK)   // 13

// ---- device scratch (allocation-free) ----
__device__ float g_xw[(size_t)N_NODES * F_OUT];     // XW, 12.8 MB
__device__ int   g_cnt[N_NODES];                    // histogram, then fill cursor
__device__ int   g_rowptr[N_NODES + 1];             // CSR row pointers
__device__ int   g_blksums[SCAN_NB];                // scan partials
__device__ int2  g_edata[N_EDGES];                  // {col, val bits} grouped by row

// ===========================================================================
// TF32 tensor-core GEMM: XW[N,64] = X[N,256] @ W[256,64]
// cvt to tf32 hoisted into the smem fill (values stored pre-rounded).
// ===========================================================================
#define GTM 128
#define GTK 32
#define XS_STR 36
#define WS_STR 72

__device__ __forceinline__ float f2tf32f(float f) {
    uint32_t u;
    asm("cvt.rna.tf32.f32 %0, %1;" : "=r"(u) : "f"(f));
    return __uint_as_float(u);
}

__global__ __launch_bounds__(256) void gemm_tf32_kernel(const float* __restrict__ X,
                                                        const float* __restrict__ W) {
    __shared__ float Xs[GTM][XS_STR];
    __shared__ float Ws[GTK][WS_STR];

    const int tid  = threadIdx.x;
    const int warp = tid >> 5;
    const int lane = tid & 31;
    const int rowBase = blockIdx.x * GTM;
    const int qid  = lane >> 2;
    const int qsub = lane & 3;

    float acc[8][4];
#pragma unroll
    for (int j = 0; j < 8; j++)
#pragma unroll
        for (int i = 0; i < 4; i++) acc[j][i] = 0.0f;

    for (int k0 = 0; k0 < F_IN; k0 += GTK) {
        // W chunk 32x64: 512 float4, 2/thread. Convert to tf32 at store.
#pragma unroll
        for (int i = 0; i < 2; i++) {
            int idx = tid + i * 256;
            int r = idx >> 4, c = idx & 15;
            float4 v = *(const float4*)(W + (size_t)(k0 + r) * F_OUT + c * 4);
            v.x = f2tf32f(v.x); v.y = f2tf32f(v.y);
            v.z = f2tf32f(v.z); v.w = f2tf32f(v.w);
            *(float4*)&Ws[r][c * 4] = v;
        }
        // X tile 128x32: 1024 float4, 4/thread. Convert to tf32 at store.
#pragma unroll
        for (int i = 0; i < 4; i++) {
            int idx = tid + i * 256;
            int r = idx >> 3, c = idx & 7;
            int gr = rowBase + r;
            float4 v = make_float4(0.f, 0.f, 0.f, 0.f);
            if (gr < N_NODES)
                v = *(const float4*)(X + (size_t)gr * F_IN + k0 + c * 4);
            v.x = f2tf32f(v.x); v.y = f2tf32f(v.y);
            v.z = f2tf32f(v.z); v.w = f2tf32f(v.w);
            *(float4*)&Xs[r][c * 4] = v;
        }
        __syncthreads();

#pragma unroll
        for (int kk = 0; kk < GTK; kk += 8) {
            const int ar = warp * 16 + qid;
            const uint32_t a0 = __float_as_uint(Xs[ar    ][kk + qsub    ]);
            const uint32_t a1 = __float_as_uint(Xs[ar + 8][kk + qsub    ]);
            const uint32_t a2 = __float_as_uint(Xs[ar    ][kk + qsub + 4]);
            const uint32_t a3 = __float_as_uint(Xs[ar + 8][kk + qsub + 4]);
#pragma unroll
            for (int j = 0; j < 8; j++) {
                const uint32_t b0 = __float_as_uint(Ws[kk + qsub    ][j * 8 + qid]);
                const uint32_t b1 = __float_as_uint(Ws[kk + qsub + 4][j * 8 + qid]);
                asm volatile(
                    "mma.sync.aligned.m16n8k8.row.col.f32.tf32.tf32.f32 "
                    "{%0,%1,%2,%3}, {%4,%5,%6,%7}, {%8,%9}, {%0,%1,%2,%3};"
                    : "+f"(acc[j][0]), "+f"(acc[j][1]), "+f"(acc[j][2]), "+f"(acc[j][3])
                    : "r"(a0), "r"(a1), "r"(a2), "r"(a3), "r"(b0), "r"(b1));
            }
        }
        __syncthreads();
    }

    const int crow = rowBase + warp * 16 + qid;
#pragma unroll
    for (int j = 0; j < 8; j++) {
        const int ccol = j * 8 + 2 * qsub;
        if (crow < N_NODES)
            *(float2*)(g_xw + (size_t)crow * F_OUT + ccol) =
                make_float2(acc[j][0], acc[j][1]);
        if (crow + 8 < N_NODES)
            *(float2*)(g_xw + (size_t)(crow + 8) * F_OUT + ccol) =
                make_float2(acc[j][2], acc[j][3]);
    }
}

// ===========================================================================
// CSR build pipeline
// ===========================================================================
__global__ __launch_bounds__(256) void zero_cnt_kernel() {
    int i = blockIdx.x * blockDim.x + threadIdx.x;
    if (i < N_NODES) g_cnt[i] = 0;
}

__global__ __launch_bounds__(256) void hist_kernel(const int* __restrict__ erow) {
    int e = blockIdx.x * blockDim.x + threadIdx.x;
    if (e < N_EDGES) atomicAdd(&g_cnt[__ldg(erow + e)], 1);
}

// Block-level exclusive scan: each block handles SCAN_CHUNK counts.
__global__ __launch_bounds__(256) void scan1_kernel() {
    __shared__ int sdata[256];
    const int tid  = threadIdx.x;
    const int base = blockIdx.x * SCAN_CHUNK + tid * 16;

    int local[16];
    int s = 0;
#pragma unroll
    for (int i = 0; i < 16; i++) {
        int idx = base + i;
        int v = (idx < N_NODES) ? g_cnt[idx] : 0;
        local[i] = s;          // exclusive within thread
        s += v;
    }
    sdata[tid] = s;
    __syncthreads();
    // Hillis-Steele inclusive scan over 256 thread sums
    for (int off = 1; off < 256; off <<= 1) {
        int t = 0;
        if (tid >= off) t = sdata[tid - off];
        __syncthreads();
        if (tid >= off) sdata[tid] += t;
        __syncthreads();
    }
    const int thrPrefix = sdata[tid] - s;   // exclusive prefix of this thread
    if (tid == 255) g_blksums[blockIdx.x] = sdata[255];
#pragma unroll
    for (int i = 0; i < 16; i++) {
        int idx = base + i;
        if (idx < N_NODES) g_rowptr[idx] = thrPrefix + local[i];
    }
}

// Exclusive scan of the SCAN_NB block sums (single warp).
__global__ __launch_bounds__(32) void scan2_kernel() {
    const int tid = threadIdx.x;
    int v = (tid < SCAN_NB) ? g_blksums[tid] : 0;
    const int orig = v;
#pragma unroll
    for (int off = 1; off < 32; off <<= 1) {
        int t = __shfl_up_sync(0xffffffffu, v, off);
        if (tid >= off) v += t;
    }
    if (tid < SCAN_NB) g_blksums[tid] = v - orig;   // exclusive
}

// Add block offsets; produce final rowptr and init fill cursor.
__global__ __launch_bounds__(256) void scan3_kernel() {
    int idx = blockIdx.x * blockDim.x + threadIdx.x;
    if (idx < N_NODES) {
        int v = g_rowptr[idx] + g_blksums[idx >> 12];   // SCAN_CHUNK == 4096
        g_rowptr[idx] = v;
        g_cnt[idx] = v;                                  // cursor
    }
    if (idx == 0) g_rowptr[N_NODES] = N_EDGES;
}

// Bucket-fill: group {col, val} by destination row.
__global__ __launch_bounds__(256) void fill_kernel(const int* __restrict__ erow,
                                                   const int* __restrict__ ecol,
                                                   const float* __restrict__ evals) {
    int e = blockIdx.x * blockDim.x + threadIdx.x;
    if (e >= N_EDGES) return;
    int r = __ldg(erow + e);
    int pos = atomicAdd(&g_cnt[r], 1);
    g_edata[pos] = make_int2(__ldg(ecol + e), __float_as_int(__ldg(evals + e)));
}

// ===========================================================================
// Gather: one warp per output row. No atomics. Each lane owns 2 columns.
// ===========================================================================
__global__ __launch_bounds__(256) void gather_kernel(float* __restrict__ out) {
    const int row  = (blockIdx.x * blockDim.x + threadIdx.x) >> 5;
    const int lane = threadIdx.x & 31;
    if (row >= N_NODES) return;

    const int s = __ldg(&g_rowptr[row]);
    const int e = __ldg(&g_rowptr[row + 1]);

    float2 acc = make_float2(0.f, 0.f);
    int i = s;
    // 4-wide software pipeline: 4 independent edge chains in flight
    for (; i + 4 <= e; i += 4) {
        const int2 e0 = g_edata[i];
        const int2 e1 = g_edata[i + 1];
        const int2 e2 = g_edata[i + 2];
        const int2 e3 = g_edata[i + 3];
        const float2 x0 = *(const float2*)(g_xw + (size_t)e0.x * F_OUT + lane * 2);
        const float2 x1 = *(const float2*)(g_xw + (size_t)e1.x * F_OUT + lane * 2);
        const float2 x2 = *(const float2*)(g_xw + (size_t)e2.x * F_OUT + lane * 2);
        const float2 x3 = *(const float2*)(g_xw + (size_t)e3.x * F_OUT + lane * 2);
        const float v0 = __int_as_float(e0.y), v1 = __int_as_float(e1.y);
        const float v2 = __int_as_float(e2.y), v3 = __int_as_float(e3.y);
        acc.x += v0 * x0.x; acc.y += v0 * x0.y;
        acc.x += v1 * x1.x; acc.y += v1 * x1.y;
        acc.x += v2 * x2.x; acc.y += v2 * x2.y;
        acc.x += v3 * x3.x; acc.y += v3 * x3.y;
    }
    for (; i < e; i++) {
        const int2 ed = g_edata[i];
        const float2 x = *(const float2*)(g_xw + (size_t)ed.x * F_OUT + lane * 2);
        const float v = __int_as_float(ed.y);
        acc.x += v * x.x; acc.y += v * x.y;
    }
    *(float2*)(out + (size_t)row * F_OUT + lane * 2) = acc;
}

// ===========================================================================
// Launch
// ===========================================================================
extern "C" void kernel_launch(void* const* d_in, const int* in_sizes, int n_in,
                              void* d_out, int out_size) {
    const float* X     = (const float*)d_in[0];
    const float* W     = (const float*)d_in[1];
    const int*   erow  = (const int*)d_in[2];
    const int*   ecol  = (const int*)d_in[3];
    const float* evals = (const float*)d_in[4];
    float* out = (float*)d_out;

    zero_cnt_kernel<<<(N_NODES + 255) / 256, 256>>>();
    gemm_tf32_kernel<<<(N_NODES + GTM - 1) / GTM, 256>>>(X, W);
    hist_kernel<<<(N_EDGES + 255) / 256, 256>>>(erow);
    scan1_kernel<<<SCAN_NB, 256>>>();
    scan2_kernel<<<1, 32>>>();
    scan3_kernel<<<(N_NODES + 255) / 256, 256>>>();
    fill_kernel<<<(N_EDGES + 255) / 256, 256>>>(erow, ecol, evals);
    gather_kernel<<<(N_NODES * 32 + 255) / 256, 256>>>(out);
}